// round 1
// baseline (speedup 1.0000x reference)
#include <cuda_runtime.h>

// ---------------------------------------------------------------------------
// GAT 2-layer forward, sparse-aware.
//   Layer1: h = x@W1 (per 2 heads), masked-softmax attention over adj rows,
//           h1 = relu(elu(concat)) == max(agg, 0)
//   Layer2: h2 = h1@W2 (256->16, 1 head), attention, mean over 1 head = out.
// ---------------------------------------------------------------------------

#define N_NODES 8192
#define F_IN    512
#define H1      128
#define KHEADS  2
#define HCAT    256      // KHEADS*H1
#define C_OUT   16
#define MAXDEG  256
#define LALPHA  0.2f

// ---- scratch (device globals; no allocation allowed) ----
__device__ int   g_adj_mode;                 // 0=u8, 1=i32, 2=f32
__device__ int   g_deg[N_NODES];
__device__ int   g_nbr[N_NODES * MAXDEG];    // 8 MB
__device__ float g_Hall[N_NODES * HCAT];     // 8 MB  layer1 hidden (pre-attn)
__device__ float g_f1s[KHEADS][N_NODES];
__device__ float g_f1d[KHEADS][N_NODES];
__device__ float g_h1[N_NODES * HCAT];       // 8 MB  layer1 output (post relu)
__device__ float g_h2[N_NODES * C_OUT];
__device__ float g_f2s[N_NODES];
__device__ float g_f2d[N_NODES];

// ---------------------------------------------------------------------------
// Probe adjacency dtype. Diagonal elements (index i*8193) are always true.
// byte[r*8193] for odd r: u8 layout -> diag element == 1; i32/f32 layout ->
// it's byte (r mod 4 != 0) of a 0/1-valued word -> always 0.
// ---------------------------------------------------------------------------
__global__ void detect_adj(const unsigned char* adj) {
    int mode;
    if (adj[8193] != 0 || adj[3 * 8193] != 0 || adj[5 * 8193] != 0) {
        mode = 0;                                     // uint8 / bool
    } else {
        const int* ai = (const int*)adj;
        mode = (ai[8193] == 1) ? 1 : 2;               // int32 vs float32
    }
    g_adj_mode = mode;
}

// ---------------------------------------------------------------------------
// CSR build: one warp per row, ballot compaction. Order within row is
// deterministic (fixed interleave), which is all we need.
// ---------------------------------------------------------------------------
__global__ __launch_bounds__(256) void build_csr(const void* adjv) {
    int warp = (blockIdx.x * blockDim.x + threadIdx.x) >> 5;
    int lane = threadIdx.x & 31;
    if (warp >= N_NODES) return;
    int row = warp;
    int mode = g_adj_mode;
    int cnt = 0;
    int* nbr = g_nbr + (size_t)row * MAXDEG;

    if (mode == 0) {
        const uchar4* p = (const uchar4*)((const unsigned char*)adjv + (size_t)row * N_NODES);
        for (int base = 0; base < N_NODES / 4; base += 32) {
            uchar4 v = p[base + lane];
            unsigned char b4[4] = { v.x, v.y, v.z, v.w };
            #pragma unroll
            for (int b = 0; b < 4; b++) {
                bool pr = (b4[b] != 0);
                unsigned m = __ballot_sync(0xFFFFFFFFu, pr);
                if (pr) {
                    int pos = cnt + __popc(m & ((1u << lane) - 1u));
                    if (pos < MAXDEG) nbr[pos] = (base + lane) * 4 + b;
                }
                cnt += __popc(m);
            }
        }
    } else if (mode == 1) {
        const int* p = (const int*)adjv + (size_t)row * N_NODES;
        for (int base = 0; base < N_NODES; base += 32) {
            bool pr = (p[base + lane] != 0);
            unsigned m = __ballot_sync(0xFFFFFFFFu, pr);
            if (pr) {
                int pos = cnt + __popc(m & ((1u << lane) - 1u));
                if (pos < MAXDEG) nbr[pos] = base + lane;
            }
            cnt += __popc(m);
        }
    } else {
        const float* p = (const float*)adjv + (size_t)row * N_NODES;
        for (int base = 0; base < N_NODES; base += 32) {
            bool pr = (p[base + lane] != 0.0f);
            unsigned m = __ballot_sync(0xFFFFFFFFu, pr);
            if (pr) {
                int pos = cnt + __popc(m & ((1u << lane) - 1u));
                if (pos < MAXDEG) nbr[pos] = base + lane;
            }
            cnt += __popc(m);
        }
    }
    if (lane == 0) g_deg[row] = (cnt < MAXDEG) ? cnt : MAXDEG;
}

// ---------------------------------------------------------------------------
// GEMM1: Hall[n][k*128+h] = sum_f x[n][f] * W1[k][f][h]
// 128x128 block tile, BK=16, 256 threads, 8x8 micro-tile. blockIdx.x == head.
// ---------------------------------------------------------------------------
#define BM 128
#define BN 128
#define BK 16

__global__ __launch_bounds__(256) void gemm1(const float* __restrict__ x,
                                             const float* __restrict__ W1) {
    __shared__ float As[BK][BM];
    __shared__ float Bs[BK][BN];
    int head = blockIdx.x;                   // BN==H1 so col-block == head
    int row0 = blockIdx.y * BM;
    int tid  = threadIdx.x;
    const float* Wh = W1 + (size_t)head * F_IN * H1;

    int tr = tid >> 4;        // 0..15
    int tc = tid & 15;        // 0..15
    float acc[8][8];
    #pragma unroll
    for (int i = 0; i < 8; i++)
        #pragma unroll
        for (int j = 0; j < 8; j++) acc[i][j] = 0.0f;

    for (int k0 = 0; k0 < F_IN; k0 += BK) {
        // A tile: 128x16 floats = 512 float4; 2 per thread (transposed store)
        #pragma unroll
        for (int it = 0; it < 2; it++) {
            int idx = it * 256 + tid;                // float4 index
            int m   = idx >> 2;                      // 4 float4 per row
            int kk  = (idx & 3) * 4;
            float4 v = *(const float4*)(x + (size_t)(row0 + m) * F_IN + k0 + kk);
            As[kk + 0][m] = v.x; As[kk + 1][m] = v.y;
            As[kk + 2][m] = v.z; As[kk + 3][m] = v.w;
        }
        // B tile: 16x128 floats = 512 float4; contiguous rows of W1[head]
        #pragma unroll
        for (int it = 0; it < 2; it++) {
            int idx = it * 256 + tid;
            int kk  = idx >> 5;                      // 32 float4 per row
            int j   = (idx & 31) * 4;
            float4 v = *(const float4*)(Wh + (size_t)(k0 + kk) * H1 + j);
            *(float4*)&Bs[kk][j] = v;
        }
        __syncthreads();
        #pragma unroll
        for (int kk = 0; kk < BK; kk++) {
            float a[8], b[8];
            #pragma unroll
            for (int i = 0; i < 8; i++) a[i] = As[kk][tr * 8 + i];
            #pragma unroll
            for (int j = 0; j < 8; j++) b[j] = Bs[kk][tc * 8 + j];
            #pragma unroll
            for (int i = 0; i < 8; i++)
                #pragma unroll
                for (int j = 0; j < 8; j++) acc[i][j] += a[i] * b[j];
        }
        __syncthreads();
    }
    #pragma unroll
    for (int i = 0; i < 8; i++) {
        int n = row0 + tr * 8 + i;
        float* o = g_Hall + (size_t)n * HCAT + head * H1 + tc * 8;
        float4 v0 = { acc[i][0], acc[i][1], acc[i][2], acc[i][3] };
        float4 v1 = { acc[i][4], acc[i][5], acc[i][6], acc[i][7] };
        *(float4*)(o + 0) = v0;
        *(float4*)(o + 4) = v1;
    }
}

// ---------------------------------------------------------------------------
// f1_src/f1_dst: one warp per (node, head); 128-d dot products
// ---------------------------------------------------------------------------
__global__ __launch_bounds__(256) void calc_f1(const float* __restrict__ a_src,
                                               const float* __restrict__ a_dst) {
    int gw   = (blockIdx.x * blockDim.x + threadIdx.x) >> 5;
    int lane = threadIdx.x & 31;
    if (gw >= N_NODES * KHEADS) return;
    int n = gw >> 1, k = gw & 1;
    const float* h  = g_Hall + (size_t)n * HCAT + k * H1;
    const float* as = a_src + k * H1;
    const float* ad = a_dst + k * H1;
    float s = 0.0f, d = 0.0f;
    #pragma unroll
    for (int r = 0; r < 4; r++) {
        float v = h[lane + 32 * r];
        s += v * as[lane + 32 * r];
        d += v * ad[lane + 32 * r];
    }
    #pragma unroll
    for (int o = 16; o; o >>= 1) {
        s += __shfl_xor_sync(0xFFFFFFFFu, s, o);
        d += __shfl_xor_sync(0xFFFFFFFFu, d, o);
    }
    if (lane == 0) { g_f1s[k][n] = s; g_f1d[k][n] = d; }
}

// ---------------------------------------------------------------------------
// Layer-1 attention + aggregate + fused relu(elu(.)) == relu
// one block (256 thr) per node; thread j owns output column j (head j>>7)
// ---------------------------------------------------------------------------
__global__ __launch_bounds__(256) void attn1() {
    int n = blockIdx.x;
    __shared__ int   s_nbr[MAXDEG];
    __shared__ float s_w[2][MAXDEG];
    __shared__ float s_red[2][2];    // [head][0]=max, [1]=sum
    int tid = threadIdx.x;
    int deg = g_deg[n];

    if (tid < deg) s_nbr[tid] = g_nbr[(size_t)n * MAXDEG + tid];
    __syncthreads();
    if (tid < deg) {
        int m = s_nbr[tid];
        #pragma unroll
        for (int k = 0; k < 2; k++) {
            float e = g_f1s[k][n] + g_f1d[k][m];
            s_w[k][tid] = (e > 0.0f) ? e : LALPHA * e;
        }
    }
    __syncthreads();
    int w = tid >> 5, lane = tid & 31;
    if (w < 2) {
        float mx = -1e30f;
        for (int i = lane; i < deg; i += 32) mx = fmaxf(mx, s_w[w][i]);
        #pragma unroll
        for (int o = 16; o; o >>= 1) mx = fmaxf(mx, __shfl_xor_sync(0xFFFFFFFFu, mx, o));
        float sm = 0.0f;
        for (int i = lane; i < deg; i += 32) sm += __expf(s_w[w][i] - mx);
        #pragma unroll
        for (int o = 16; o; o >>= 1) sm += __shfl_xor_sync(0xFFFFFFFFu, sm, o);
        if (lane == 0) { s_red[w][0] = mx; s_red[w][1] = sm; }
    }
    __syncthreads();
    if (tid < deg) {
        #pragma unroll
        for (int k = 0; k < 2; k++)
            s_w[k][tid] = __expf(s_w[k][tid] - s_red[k][0]) / s_red[k][1];
    }
    __syncthreads();

    int k = tid >> 7;
    float acc = 0.0f;
    for (int i = 0; i < deg; i++)
        acc = fmaf(s_w[k][i], g_Hall[(size_t)s_nbr[i] * HCAT + tid], acc);
    g_h1[(size_t)n * HCAT + tid] = fmaxf(acc, 0.0f);   // relu(elu(z)) == relu(z)
}

// ---------------------------------------------------------------------------
// Layer-2 GEMM (256->16) + f2_src/f2_dst: one warp per node
// ---------------------------------------------------------------------------
__global__ __launch_bounds__(256) void layer2_gemm(const float* __restrict__ W2,
                                                   const float* __restrict__ a2s,
                                                   const float* __restrict__ a2d) {
    int gw   = (blockIdx.x * blockDim.x + threadIdx.x) >> 5;
    int lane = threadIdx.x & 31;
    if (gw >= N_NODES) return;
    int n = gw;
    const float* hr = g_h1 + (size_t)n * HCAT;
    float h[8];
    #pragma unroll
    for (int r = 0; r < 8; r++) h[r] = hr[lane + 32 * r];
    float fs = 0.0f, fd = 0.0f;
    #pragma unroll
    for (int c = 0; c < C_OUT; c++) {
        float acc = 0.0f;
        #pragma unroll
        for (int r = 0; r < 8; r++)
            acc = fmaf(h[r], W2[(size_t)(lane + 32 * r) * C_OUT + c], acc);
        #pragma unroll
        for (int o = 16; o; o >>= 1) acc += __shfl_xor_sync(0xFFFFFFFFu, acc, o);
        if (lane == 0) {
            g_h2[n * C_OUT + c] = acc;
            fs = fmaf(acc, a2s[c], fs);
            fd = fmaf(acc, a2d[c], fd);
        }
    }
    if (lane == 0) { g_f2s[n] = fs; g_f2d[n] = fd; }
}

// ---------------------------------------------------------------------------
// Layer-2 attention + aggregate (C=16, single head, mean over 1 head = id)
// one warp per node; 8 warps per block
// ---------------------------------------------------------------------------
__global__ __launch_bounds__(256) void attn2(float* __restrict__ out) {
    __shared__ float s_w[8][MAXDEG];
    int wIn = threadIdx.x >> 5, lane = threadIdx.x & 31;
    int n = blockIdx.x * 8 + wIn;
    if (n >= N_NODES) return;
    int deg = g_deg[n];
    const int* nbr = g_nbr + (size_t)n * MAXDEG;
    float fsn = g_f2s[n];

    float mx = -1e30f;
    for (int i = lane; i < deg; i += 32) {
        int m = nbr[i];
        float e = fsn + g_f2d[m];
        e = (e > 0.0f) ? e : LALPHA * e;
        s_w[wIn][i] = e;
        mx = fmaxf(mx, e);
    }
    #pragma unroll
    for (int o = 16; o; o >>= 1) mx = fmaxf(mx, __shfl_xor_sync(0xFFFFFFFFu, mx, o));
    float sm = 0.0f;
    for (int i = lane; i < deg; i += 32) {
        float v = __expf(s_w[wIn][i] - mx);
        s_w[wIn][i] = v;
        sm += v;
    }
    #pragma unroll
    for (int o = 16; o; o >>= 1) sm += __shfl_xor_sync(0xFFFFFFFFu, sm, o);
    float inv = 1.0f / sm;
    __syncwarp();
    if (lane < C_OUT) {
        float acc = 0.0f;
        for (int i = 0; i < deg; i++)
            acc = fmaf(s_w[wIn][i], g_h2[(size_t)nbr[i] * C_OUT + lane], acc);
        out[(size_t)n * C_OUT + lane] = acc * inv;
    }
}

// ---------------------------------------------------------------------------
extern "C" void kernel_launch(void* const* d_in, const int* in_sizes, int n_in,
                              void* d_out, int out_size) {
    const float* x   = (const float*)d_in[0];
    const void*  adj = d_in[1];
    const float* W1  = (const float*)d_in[2];
    const float* a1s = (const float*)d_in[3];
    const float* a1d = (const float*)d_in[4];
    const float* W2  = (const float*)d_in[5];
    const float* a2s = (const float*)d_in[6];
    const float* a2d = (const float*)d_in[7];
    float* out = (float*)d_out;

    detect_adj<<<1, 1>>>((const unsigned char*)adj);
    build_csr<<<N_NODES / 8, 256>>>(adj);

    dim3 g1(HCAT / BN, N_NODES / BM);          // (2, 64)
    gemm1<<<g1, 256>>>(x, W1);

    calc_f1<<<(N_NODES * KHEADS) / 8, 256>>>(a1s, a1d);
    attn1<<<N_NODES, 256>>>();
    layer2_gemm<<<N_NODES / 8, 256>>>(W2, a2s, a2d);
    attn2<<<N_NODES / 8, 256>>>(out);
}

// round 2
// speedup vs baseline: 1.0865x; 1.0865x over previous
#include <cuda_runtime.h>

// ---------------------------------------------------------------------------
// GAT 2-layer forward, sparse-aware. Round 2: GEMM1 on tensor cores
// (tf32 mma.sync, 3-term split for fp32-grade accuracy) with fused f1 epilogue.
// ---------------------------------------------------------------------------

#define N_NODES 8192
#define F_IN    512
#define H1      128
#define KHEADS  2
#define HCAT    256
#define C_OUT   16
#define MAXDEG  256
#define LALPHA  0.2f

// ---- scratch (device globals; no allocation allowed) ----
__device__ int   g_adj_mode;
__device__ int   g_deg[N_NODES];
__device__ int   g_nbr[N_NODES * MAXDEG];
__device__ float g_Hall[N_NODES * HCAT];
__device__ float g_f1s[KHEADS][N_NODES];
__device__ float g_f1d[KHEADS][N_NODES];
__device__ float g_h1[N_NODES * HCAT];
__device__ float g_h2[N_NODES * C_OUT];
__device__ float g_f2s[N_NODES];
__device__ float g_f2d[N_NODES];

// ---------------------------------------------------------------------------
__global__ void detect_adj(const unsigned char* adj) {
    int mode;
    if (adj[8193] != 0 || adj[3 * 8193] != 0 || adj[5 * 8193] != 0) {
        mode = 0;
    } else {
        const int* ai = (const int*)adj;
        mode = (ai[8193] == 1) ? 1 : 2;
    }
    g_adj_mode = mode;
}

// ---------------------------------------------------------------------------
__global__ __launch_bounds__(256) void build_csr(const void* adjv) {
    int warp = (blockIdx.x * blockDim.x + threadIdx.x) >> 5;
    int lane = threadIdx.x & 31;
    if (warp >= N_NODES) return;
    int row = warp;
    int mode = g_adj_mode;
    int cnt = 0;
    int* nbr = g_nbr + (size_t)row * MAXDEG;

    if (mode == 0) {
        const uchar4* p = (const uchar4*)((const unsigned char*)adjv + (size_t)row * N_NODES);
        for (int base = 0; base < N_NODES / 4; base += 32) {
            uchar4 v = p[base + lane];
            unsigned char b4[4] = { v.x, v.y, v.z, v.w };
            #pragma unroll
            for (int b = 0; b < 4; b++) {
                bool pr = (b4[b] != 0);
                unsigned m = __ballot_sync(0xFFFFFFFFu, pr);
                if (pr) {
                    int pos = cnt + __popc(m & ((1u << lane) - 1u));
                    if (pos < MAXDEG) nbr[pos] = (base + lane) * 4 + b;
                }
                cnt += __popc(m);
            }
        }
    } else if (mode == 1) {
        const int* p = (const int*)adjv + (size_t)row * N_NODES;
        for (int base = 0; base < N_NODES; base += 32) {
            bool pr = (p[base + lane] != 0);
            unsigned m = __ballot_sync(0xFFFFFFFFu, pr);
            if (pr) {
                int pos = cnt + __popc(m & ((1u << lane) - 1u));
                if (pos < MAXDEG) nbr[pos] = base + lane;
            }
            cnt += __popc(m);
        }
    } else {
        const float* p = (const float*)adjv + (size_t)row * N_NODES;
        for (int base = 0; base < N_NODES; base += 32) {
            bool pr = (p[base + lane] != 0.0f);
            unsigned m = __ballot_sync(0xFFFFFFFFu, pr);
            if (pr) {
                int pos = cnt + __popc(m & ((1u << lane) - 1u));
                if (pos < MAXDEG) nbr[pos] = base + lane;
            }
            cnt += __popc(m);
        }
    }
    if (lane == 0) g_deg[row] = (cnt < MAXDEG) ? cnt : MAXDEG;
}

// ---------------------------------------------------------------------------
// GEMM1 on tensor cores: Hall[n][head*128+h] = sum_f x[n][f] * W1[head][f][h]
// tf32 mma.sync m16n8k8, 3-term split (hi*hi + hi*lo + lo*hi) ~ fp32 accuracy.
// Block: 128(M) x 128(N=head dim), BK=16, 256 threads = 8 warps (2m x 4n),
// warp tile 64x32. Fused epilogue computes f1s/f1d per row.
// ---------------------------------------------------------------------------
#define BM 128
#define BK 16
#define A_STRIDE 20     // conflict-free: (20*(lane>>2)+lane%4) mod 32 is a bijection
#define B_STRIDE 136    // conflict-free: (136*(lane%4)+lane>>2) mod 32 is a bijection

__device__ __forceinline__ void split_tf32(float v, unsigned& hi, unsigned& lo) {
    asm("cvt.rna.tf32.f32 %0, %1;" : "=r"(hi) : "f"(v));
    float r = v - __uint_as_float(hi);
    asm("cvt.rna.tf32.f32 %0, %1;" : "=r"(lo) : "f"(r));
}

#define MMA_TF32(c, a0, a1, a2, a3, b0, b1)                                     \
    asm volatile(                                                               \
        "mma.sync.aligned.m16n8k8.row.col.f32.tf32.tf32.f32 "                   \
        "{%0,%1,%2,%3},{%4,%5,%6,%7},{%8,%9},{%0,%1,%2,%3};"                    \
        : "+f"(c[0]), "+f"(c[1]), "+f"(c[2]), "+f"(c[3])                        \
        : "r"(a0), "r"(a1), "r"(a2), "r"(a3), "r"(b0), "r"(b1))

__global__ __launch_bounds__(256, 1) void gemm1_tc(const float* __restrict__ x,
                                                   const float* __restrict__ W1,
                                                   const float* __restrict__ a1s,
                                                   const float* __restrict__ a1d) {
    __shared__ unsigned As_hi[BM][A_STRIDE];
    __shared__ unsigned As_lo[BM][A_STRIDE];
    __shared__ unsigned Bs_hi[BK][B_STRIDE];
    __shared__ unsigned Bs_lo[BK][B_STRIDE];
    __shared__ float sh_s[BM];
    __shared__ float sh_d[BM];

    const int head = blockIdx.x;
    const int row0 = blockIdx.y * BM;
    const int tid  = threadIdx.x;
    const int warp = tid >> 5;
    const int lane = tid & 31;
    const int warpM = warp >> 2;    // 0..1
    const int warpN = warp & 3;     // 0..3
    const float* Wh = W1 + (size_t)head * F_IN * H1;

    if (tid < BM) { sh_s[tid] = 0.0f; sh_d[tid] = 0.0f; }

    float acc[4][4][4];
    #pragma unroll
    for (int mt = 0; mt < 4; mt++)
        #pragma unroll
        for (int nt = 0; nt < 4; nt++)
            #pragma unroll
            for (int r = 0; r < 4; r++) acc[mt][nt][r] = 0.0f;

    // gmem prefetch registers
    float4 ax[2], bw[2];
    // loader index maps
    const int aM[2]  = { (0 * 256 + tid) >> 2,       (1 * 256 + tid) >> 2 };
    const int aK4[2] = { ((0 * 256 + tid) & 3) * 4,  ((1 * 256 + tid) & 3) * 4 };
    const int bK[2]  = { (0 * 256 + tid) >> 5,       (1 * 256 + tid) >> 5 };
    const int bN4[2] = { ((0 * 256 + tid) & 31) * 4, ((1 * 256 + tid) & 31) * 4 };

    #pragma unroll
    for (int it = 0; it < 2; it++) {
        ax[it] = *(const float4*)(x  + (size_t)(row0 + aM[it]) * F_IN + aK4[it]);
        bw[it] = *(const float4*)(Wh + (size_t)bK[it] * H1 + bN4[it]);
    }

    for (int k0 = 0; k0 < F_IN; k0 += BK) {
        // store (with tf32 hi/lo split) into smem
        #pragma unroll
        for (int it = 0; it < 2; it++) {
            uint4 h, l;
            split_tf32(ax[it].x, h.x, l.x);
            split_tf32(ax[it].y, h.y, l.y);
            split_tf32(ax[it].z, h.z, l.z);
            split_tf32(ax[it].w, h.w, l.w);
            *(uint4*)&As_hi[aM[it]][aK4[it]] = h;
            *(uint4*)&As_lo[aM[it]][aK4[it]] = l;
            split_tf32(bw[it].x, h.x, l.x);
            split_tf32(bw[it].y, h.y, l.y);
            split_tf32(bw[it].z, h.z, l.z);
            split_tf32(bw[it].w, h.w, l.w);
            *(uint4*)&Bs_hi[bK[it]][bN4[it]] = h;
            *(uint4*)&Bs_lo[bK[it]][bN4[it]] = l;
        }
        __syncthreads();

        // prefetch next K tile
        if (k0 + BK < F_IN) {
            #pragma unroll
            for (int it = 0; it < 2; it++) {
                ax[it] = *(const float4*)(x  + (size_t)(row0 + aM[it]) * F_IN + (k0 + BK) + aK4[it]);
                bw[it] = *(const float4*)(Wh + (size_t)(k0 + BK + bK[it]) * H1 + bN4[it]);
            }
        }

        // compute: 2 k8 steps
        #pragma unroll
        for (int ks = 0; ks < 2; ks++) {
            const int kb = ks * 8;
            unsigned ah[4][4], al[4][4], bh[4][2], bl[4][2];
            const int ar = warpM * 64 + (lane >> 2);
            const int kc = kb + (lane & 3);
            #pragma unroll
            for (int mt = 0; mt < 4; mt++) {
                int r = ar + mt * 16;
                ah[mt][0] = As_hi[r][kc];     ah[mt][1] = As_hi[r + 8][kc];
                ah[mt][2] = As_hi[r][kc + 4]; ah[mt][3] = As_hi[r + 8][kc + 4];
                al[mt][0] = As_lo[r][kc];     al[mt][1] = As_lo[r + 8][kc];
                al[mt][2] = As_lo[r][kc + 4]; al[mt][3] = As_lo[r + 8][kc + 4];
            }
            const int bn = warpN * 32 + (lane >> 2);
            const int kr = kb + (lane & 3);
            #pragma unroll
            for (int nt = 0; nt < 4; nt++) {
                bh[nt][0] = Bs_hi[kr][bn + nt * 8];
                bh[nt][1] = Bs_hi[kr + 4][bn + nt * 8];
                bl[nt][0] = Bs_lo[kr][bn + nt * 8];
                bl[nt][1] = Bs_lo[kr + 4][bn + nt * 8];
            }
            #pragma unroll
            for (int mt = 0; mt < 4; mt++)
                #pragma unroll
                for (int nt = 0; nt < 4; nt++) {
                    MMA_TF32(acc[mt][nt], ah[mt][0], ah[mt][1], ah[mt][2], ah[mt][3],
                             bh[nt][0], bh[nt][1]);
                    MMA_TF32(acc[mt][nt], ah[mt][0], ah[mt][1], ah[mt][2], ah[mt][3],
                             bl[nt][0], bl[nt][1]);
                    MMA_TF32(acc[mt][nt], al[mt][0], al[mt][1], al[mt][2], al[mt][3],
                             bh[nt][0], bh[nt][1]);
                }
        }
        __syncthreads();
    }

    // ---- epilogue: store Hall + fused f1s/f1d ----
    float asv[4][2], adv[4][2];
    const int colb = warpN * 32;
    #pragma unroll
    for (int nt = 0; nt < 4; nt++) {
        int c = colb + nt * 8 + 2 * (lane & 3);
        asv[nt][0] = a1s[head * H1 + c];
        asv[nt][1] = a1s[head * H1 + c + 1];
        adv[nt][0] = a1d[head * H1 + c];
        adv[nt][1] = a1d[head * H1 + c + 1];
    }

    #pragma unroll
    for (int mt = 0; mt < 4; mt++) {
        float s0 = 0.f, s1 = 0.f, d0 = 0.f, d1 = 0.f;
        #pragma unroll
        for (int nt = 0; nt < 4; nt++) {
            s0 += acc[mt][nt][0] * asv[nt][0] + acc[mt][nt][1] * asv[nt][1];
            s1 += acc[mt][nt][2] * asv[nt][0] + acc[mt][nt][3] * asv[nt][1];
            d0 += acc[mt][nt][0] * adv[nt][0] + acc[mt][nt][1] * adv[nt][1];
            d1 += acc[mt][nt][2] * adv[nt][0] + acc[mt][nt][3] * adv[nt][1];
        }
        #pragma unroll
        for (int o = 1; o <= 2; o <<= 1) {
            s0 += __shfl_xor_sync(0xFFFFFFFFu, s0, o);
            s1 += __shfl_xor_sync(0xFFFFFFFFu, s1, o);
            d0 += __shfl_xor_sync(0xFFFFFFFFu, d0, o);
            d1 += __shfl_xor_sync(0xFFFFFFFFu, d1, o);
        }
        int rl = warpM * 64 + mt * 16 + (lane >> 2);
        if ((lane & 3) == 0) {
            atomicAdd(&sh_s[rl], s0);     atomicAdd(&sh_d[rl], d0);
            atomicAdd(&sh_s[rl + 8], s1); atomicAdd(&sh_d[rl + 8], d1);
        }
        // store Hall
        int gr0 = row0 + rl;
        #pragma unroll
        for (int nt = 0; nt < 4; nt++) {
            int c = head * H1 + colb + nt * 8 + 2 * (lane & 3);
            float2 v0 = { acc[mt][nt][0], acc[mt][nt][1] };
            float2 v1 = { acc[mt][nt][2], acc[mt][nt][3] };
            *(float2*)&g_Hall[(size_t)gr0 * HCAT + c]       = v0;
            *(float2*)&g_Hall[(size_t)(gr0 + 8) * HCAT + c] = v1;
        }
    }
    __syncthreads();
    if (tid < BM) {
        g_f1s[head][row0 + tid] = sh_s[tid];
        g_f1d[head][row0 + tid] = sh_d[tid];
    }
}

// ---------------------------------------------------------------------------
// Layer-1 attention + aggregate + relu(elu(.)) == relu
// ---------------------------------------------------------------------------
__global__ __launch_bounds__(256) void attn1() {
    int n = blockIdx.x;
    __shared__ int   s_nbr[MAXDEG];
    __shared__ float s_w[2][MAXDEG];
    __shared__ float s_red[2][2];
    int tid = threadIdx.x;
    int deg = g_deg[n];

    if (tid < deg) s_nbr[tid] = g_nbr[(size_t)n * MAXDEG + tid];
    __syncthreads();
    if (tid < deg) {
        int m = s_nbr[tid];
        #pragma unroll
        for (int k = 0; k < 2; k++) {
            float e = g_f1s[k][n] + g_f1d[k][m];
            s_w[k][tid] = (e > 0.0f) ? e : LALPHA * e;
        }
    }
    __syncthreads();
    int w = tid >> 5, lane = tid & 31;
    if (w < 2) {
        float mx = -1e30f;
        for (int i = lane; i < deg; i += 32) mx = fmaxf(mx, s_w[w][i]);
        #pragma unroll
        for (int o = 16; o; o >>= 1) mx = fmaxf(mx, __shfl_xor_sync(0xFFFFFFFFu, mx, o));
        float sm = 0.0f;
        for (int i = lane; i < deg; i += 32) sm += __expf(s_w[w][i] - mx);
        #pragma unroll
        for (int o = 16; o; o >>= 1) sm += __shfl_xor_sync(0xFFFFFFFFu, sm, o);
        if (lane == 0) { s_red[w][0] = mx; s_red[w][1] = sm; }
    }
    __syncthreads();
    if (tid < deg) {
        #pragma unroll
        for (int k = 0; k < 2; k++)
            s_w[k][tid] = __expf(s_w[k][tid] - s_red[k][0]) / s_red[k][1];
    }
    __syncthreads();

    int k = tid >> 7;
    float acc = 0.0f;
    for (int i = 0; i < deg; i++)
        acc = fmaf(s_w[k][i], g_Hall[(size_t)s_nbr[i] * HCAT + tid], acc);
    g_h1[(size_t)n * HCAT + tid] = fmaxf(acc, 0.0f);
}

// ---------------------------------------------------------------------------
__global__ __launch_bounds__(256) void layer2_gemm(const float* __restrict__ W2,
                                                   const float* __restrict__ a2s,
                                                   const float* __restrict__ a2d) {
    int gw   = (blockIdx.x * blockDim.x + threadIdx.x) >> 5;
    int lane = threadIdx.x & 31;
    if (gw >= N_NODES) return;
    int n = gw;
    const float* hr = g_h1 + (size_t)n * HCAT;
    float h[8];
    #pragma unroll
    for (int r = 0; r < 8; r++) h[r] = hr[lane + 32 * r];
    float fs = 0.0f, fd = 0.0f;
    #pragma unroll
    for (int c = 0; c < C_OUT; c++) {
        float acc = 0.0f;
        #pragma unroll
        for (int r = 0; r < 8; r++)
            acc = fmaf(h[r], W2[(size_t)(lane + 32 * r) * C_OUT + c], acc);
        #pragma unroll
        for (int o = 16; o; o >>= 1) acc += __shfl_xor_sync(0xFFFFFFFFu, acc, o);
        if (lane == 0) {
            g_h2[n * C_OUT + c] = acc;
            fs = fmaf(acc, a2s[c], fs);
            fd = fmaf(acc, a2d[c], fd);
        }
    }
    if (lane == 0) { g_f2s[n] = fs; g_f2d[n] = fd; }
}

// ---------------------------------------------------------------------------
__global__ __launch_bounds__(256) void attn2(float* __restrict__ out) {
    __shared__ float s_w[8][MAXDEG];
    int wIn = threadIdx.x >> 5, lane = threadIdx.x & 31;
    int n = blockIdx.x * 8 + wIn;
    if (n >= N_NODES) return;
    int deg = g_deg[n];
    const int* nbr = g_nbr + (size_t)n * MAXDEG;
    float fsn = g_f2s[n];

    float mx = -1e30f;
    for (int i = lane; i < deg; i += 32) {
        int m = nbr[i];
        float e = fsn + g_f2d[m];
        e = (e > 0.0f) ? e : LALPHA * e;
        s_w[wIn][i] = e;
        mx = fmaxf(mx, e);
    }
    #pragma unroll
    for (int o = 16; o; o >>= 1) mx = fmaxf(mx, __shfl_xor_sync(0xFFFFFFFFu, mx, o));
    float sm = 0.0f;
    for (int i = lane; i < deg; i += 32) {
        float v = __expf(s_w[wIn][i] - mx);
        s_w[wIn][i] = v;
        sm += v;
    }
    #pragma unroll
    for (int o = 16; o; o >>= 1) sm += __shfl_xor_sync(0xFFFFFFFFu, sm, o);
    float inv = 1.0f / sm;
    __syncwarp();
    if (lane < C_OUT) {
        float acc = 0.0f;
        for (int i = 0; i < deg; i++)
            acc = fmaf(s_w[wIn][i], g_h2[(size_t)nbr[i] * C_OUT + lane], acc);
        out[(size_t)n * C_OUT + lane] = acc * inv;
    }
}

// ---------------------------------------------------------------------------
extern "C" void kernel_launch(void* const* d_in, const int* in_sizes, int n_in,
                              void* d_out, int out_size) {
    const float* x   = (const float*)d_in[0];
    const void*  adj = d_in[1];
    const float* W1  = (const float*)d_in[2];
    const float* a1s = (const float*)d_in[3];
    const float* a1d = (const float*)d_in[4];
    const float* W2  = (const float*)d_in[5];
    const float* a2s = (const float*)d_in[6];
    const float* a2d = (const float*)d_in[7];
    float* out = (float*)d_out;

    detect_adj<<<1, 1>>>((const unsigned char*)adj);
    build_csr<<<N_NODES / 8, 256>>>(adj);

    dim3 g1(KHEADS, N_NODES / BM);             // (2, 64)
    gemm1_tc<<<g1, 256>>>(x, W1, a1s, a1d);

    attn1<<<N_NODES, 256>>>();
    layer2_gemm<<<N_NODES / 8, 256>>>(W2, a2s, a2d);
    attn2<<<N_NODES / 8, 256>>>(out);
}

// round 3
// speedup vs baseline: 1.3704x; 1.2612x over previous
#include <cuda_runtime.h>

// ---------------------------------------------------------------------------
// GAT 2-layer forward, sparse-aware.
// Round 3: attn1 float4 neighbor-parallel aggregation + fused layer-2 GEMM,
// lane-parallel attn2, detect folded into build_csr.
// ---------------------------------------------------------------------------

#define N_NODES 8192
#define F_IN    512
#define H1      128
#define KHEADS  2
#define HCAT    256
#define C_OUT   16
#define MAXDEG  256
#define LALPHA  0.2f

// ---- scratch (device globals; no allocation allowed) ----
__device__ int   g_deg[N_NODES];
__device__ int   g_nbr[N_NODES * MAXDEG];
__device__ float g_Hall[N_NODES * HCAT];
__device__ float g_f1s[KHEADS][N_NODES];
__device__ float g_f1d[KHEADS][N_NODES];
__device__ float g_h2[N_NODES * C_OUT];
__device__ float g_f2s[N_NODES];
__device__ float g_f2d[N_NODES];

// ---------------------------------------------------------------------------
// CSR build, one warp per row; adjacency dtype probed inline per warp
// (diagonal self-loops guaranteed: byte[i*8193] for odd i distinguishes u8).
// ---------------------------------------------------------------------------
__global__ __launch_bounds__(256) void build_csr(const void* adjv) {
    int warp = (blockIdx.x * blockDim.x + threadIdx.x) >> 5;
    int lane = threadIdx.x & 31;
    if (warp >= N_NODES) return;
    int row = warp;

    const unsigned char* a8 = (const unsigned char*)adjv;
    int mode;
    if ((a8[8193] | a8[3 * 8193] | a8[5 * 8193]) != 0) mode = 0;
    else mode = (((const int*)adjv)[8193] == 1) ? 1 : 2;

    int cnt = 0;
    int* nbr = g_nbr + (size_t)row * MAXDEG;

    if (mode == 0) {
        const uchar4* p = (const uchar4*)(a8 + (size_t)row * N_NODES);
        for (int base = 0; base < N_NODES / 4; base += 32) {
            uchar4 v = p[base + lane];
            unsigned char b4[4] = { v.x, v.y, v.z, v.w };
            #pragma unroll
            for (int b = 0; b < 4; b++) {
                bool pr = (b4[b] != 0);
                unsigned m = __ballot_sync(0xFFFFFFFFu, pr);
                if (pr) {
                    int pos = cnt + __popc(m & ((1u << lane) - 1u));
                    if (pos < MAXDEG) nbr[pos] = (base + lane) * 4 + b;
                }
                cnt += __popc(m);
            }
        }
    } else if (mode == 1) {
        const int* p = (const int*)adjv + (size_t)row * N_NODES;
        for (int base = 0; base < N_NODES; base += 32) {
            bool pr = (p[base + lane] != 0);
            unsigned m = __ballot_sync(0xFFFFFFFFu, pr);
            if (pr) {
                int pos = cnt + __popc(m & ((1u << lane) - 1u));
                if (pos < MAXDEG) nbr[pos] = base + lane;
            }
            cnt += __popc(m);
        }
    } else {
        const float* p = (const float*)adjv + (size_t)row * N_NODES;
        for (int base = 0; base < N_NODES; base += 32) {
            bool pr = (p[base + lane] != 0.0f);
            unsigned m = __ballot_sync(0xFFFFFFFFu, pr);
            if (pr) {
                int pos = cnt + __popc(m & ((1u << lane) - 1u));
                if (pos < MAXDEG) nbr[pos] = base + lane;
            }
            cnt += __popc(m);
        }
    }
    if (lane == 0) g_deg[row] = (cnt < MAXDEG) ? cnt : MAXDEG;
}

// ---------------------------------------------------------------------------
// GEMM1 on tensor cores (tf32 3-term split), fused f1s/f1d epilogue.
// ---------------------------------------------------------------------------
#define BM 128
#define BK 16
#define A_STRIDE 20
#define B_STRIDE 136

__device__ __forceinline__ void split_tf32(float v, unsigned& hi, unsigned& lo) {
    asm("cvt.rna.tf32.f32 %0, %1;" : "=r"(hi) : "f"(v));
    float r = v - __uint_as_float(hi);
    asm("cvt.rna.tf32.f32 %0, %1;" : "=r"(lo) : "f"(r));
}

#define MMA_TF32(c, a0, a1, a2, a3, b0, b1)                                     \
    asm volatile(                                                               \
        "mma.sync.aligned.m16n8k8.row.col.f32.tf32.tf32.f32 "                   \
        "{%0,%1,%2,%3},{%4,%5,%6,%7},{%8,%9},{%0,%1,%2,%3};"                    \
        : "+f"(c[0]), "+f"(c[1]), "+f"(c[2]), "+f"(c[3])                        \
        : "r"(a0), "r"(a1), "r"(a2), "r"(a3), "r"(b0), "r"(b1))

__global__ __launch_bounds__(256, 1) void gemm1_tc(const float* __restrict__ x,
                                                   const float* __restrict__ W1,
                                                   const float* __restrict__ a1s,
                                                   const float* __restrict__ a1d) {
    __shared__ unsigned As_hi[BM][A_STRIDE];
    __shared__ unsigned As_lo[BM][A_STRIDE];
    __shared__ unsigned Bs_hi[BK][B_STRIDE];
    __shared__ unsigned Bs_lo[BK][B_STRIDE];
    __shared__ float sh_s[BM];
    __shared__ float sh_d[BM];

    const int head = blockIdx.x;
    const int row0 = blockIdx.y * BM;
    const int tid  = threadIdx.x;
    const int warp = tid >> 5;
    const int lane = tid & 31;
    const int warpM = warp >> 2;
    const int warpN = warp & 3;
    const float* Wh = W1 + (size_t)head * F_IN * H1;

    if (tid < BM) { sh_s[tid] = 0.0f; sh_d[tid] = 0.0f; }

    float acc[4][4][4];
    #pragma unroll
    for (int mt = 0; mt < 4; mt++)
        #pragma unroll
        for (int nt = 0; nt < 4; nt++)
            #pragma unroll
            for (int r = 0; r < 4; r++) acc[mt][nt][r] = 0.0f;

    float4 ax[2], bw[2];
    const int aM[2]  = { (0 * 256 + tid) >> 2,       (1 * 256 + tid) >> 2 };
    const int aK4[2] = { ((0 * 256 + tid) & 3) * 4,  ((1 * 256 + tid) & 3) * 4 };
    const int bK[2]  = { (0 * 256 + tid) >> 5,       (1 * 256 + tid) >> 5 };
    const int bN4[2] = { ((0 * 256 + tid) & 31) * 4, ((1 * 256 + tid) & 31) * 4 };

    #pragma unroll
    for (int it = 0; it < 2; it++) {
        ax[it] = *(const float4*)(x  + (size_t)(row0 + aM[it]) * F_IN + aK4[it]);
        bw[it] = *(const float4*)(Wh + (size_t)bK[it] * H1 + bN4[it]);
    }

    for (int k0 = 0; k0 < F_IN; k0 += BK) {
        #pragma unroll
        for (int it = 0; it < 2; it++) {
            uint4 h, l;
            split_tf32(ax[it].x, h.x, l.x);
            split_tf32(ax[it].y, h.y, l.y);
            split_tf32(ax[it].z, h.z, l.z);
            split_tf32(ax[it].w, h.w, l.w);
            *(uint4*)&As_hi[aM[it]][aK4[it]] = h;
            *(uint4*)&As_lo[aM[it]][aK4[it]] = l;
            split_tf32(bw[it].x, h.x, l.x);
            split_tf32(bw[it].y, h.y, l.y);
            split_tf32(bw[it].z, h.z, l.z);
            split_tf32(bw[it].w, h.w, l.w);
            *(uint4*)&Bs_hi[bK[it]][bN4[it]] = h;
            *(uint4*)&Bs_lo[bK[it]][bN4[it]] = l;
        }
        __syncthreads();

        if (k0 + BK < F_IN) {
            #pragma unroll
            for (int it = 0; it < 2; it++) {
                ax[it] = *(const float4*)(x  + (size_t)(row0 + aM[it]) * F_IN + (k0 + BK) + aK4[it]);
                bw[it] = *(const float4*)(Wh + (size_t)(k0 + BK + bK[it]) * H1 + bN4[it]);
            }
        }

        #pragma unroll
        for (int ks = 0; ks < 2; ks++) {
            const int kb = ks * 8;
            unsigned ah[4][4], al[4][4], bh[4][2], bl[4][2];
            const int ar = warpM * 64 + (lane >> 2);
            const int kc = kb + (lane & 3);
            #pragma unroll
            for (int mt = 0; mt < 4; mt++) {
                int r = ar + mt * 16;
                ah[mt][0] = As_hi[r][kc];     ah[mt][1] = As_hi[r + 8][kc];
                ah[mt][2] = As_hi[r][kc + 4]; ah[mt][3] = As_hi[r + 8][kc + 4];
                al[mt][0] = As_lo[r][kc];     al[mt][1] = As_lo[r + 8][kc];
                al[mt][2] = As_lo[r][kc + 4]; al[mt][3] = As_lo[r + 8][kc + 4];
            }
            const int bn = warpN * 32 + (lane >> 2);
            const int kr = kb + (lane & 3);
            #pragma unroll
            for (int nt = 0; nt < 4; nt++) {
                bh[nt][0] = Bs_hi[kr][bn + nt * 8];
                bh[nt][1] = Bs_hi[kr + 4][bn + nt * 8];
                bl[nt][0] = Bs_lo[kr][bn + nt * 8];
                bl[nt][1] = Bs_lo[kr + 4][bn + nt * 8];
            }
            #pragma unroll
            for (int mt = 0; mt < 4; mt++)
                #pragma unroll
                for (int nt = 0; nt < 4; nt++) {
                    MMA_TF32(acc[mt][nt], ah[mt][0], ah[mt][1], ah[mt][2], ah[mt][3],
                             bh[nt][0], bh[nt][1]);
                    MMA_TF32(acc[mt][nt], ah[mt][0], ah[mt][1], ah[mt][2], ah[mt][3],
                             bl[nt][0], bl[nt][1]);
                    MMA_TF32(acc[mt][nt], al[mt][0], al[mt][1], al[mt][2], al[mt][3],
                             bh[nt][0], bh[nt][1]);
                }
        }
        __syncthreads();
    }

    float asv[4][2], adv[4][2];
    const int colb = warpN * 32;
    #pragma unroll
    for (int nt = 0; nt < 4; nt++) {
        int c = colb + nt * 8 + 2 * (lane & 3);
        asv[nt][0] = a1s[head * H1 + c];
        asv[nt][1] = a1s[head * H1 + c + 1];
        adv[nt][0] = a1d[head * H1 + c];
        adv[nt][1] = a1d[head * H1 + c + 1];
    }

    #pragma unroll
    for (int mt = 0; mt < 4; mt++) {
        float s0 = 0.f, s1 = 0.f, d0 = 0.f, d1 = 0.f;
        #pragma unroll
        for (int nt = 0; nt < 4; nt++) {
            s0 += acc[mt][nt][0] * asv[nt][0] + acc[mt][nt][1] * asv[nt][1];
            s1 += acc[mt][nt][2] * asv[nt][0] + acc[mt][nt][3] * asv[nt][1];
            d0 += acc[mt][nt][0] * adv[nt][0] + acc[mt][nt][1] * adv[nt][1];
            d1 += acc[mt][nt][2] * adv[nt][0] + acc[mt][nt][3] * adv[nt][1];
        }
        #pragma unroll
        for (int o = 1; o <= 2; o <<= 1) {
            s0 += __shfl_xor_sync(0xFFFFFFFFu, s0, o);
            s1 += __shfl_xor_sync(0xFFFFFFFFu, s1, o);
            d0 += __shfl_xor_sync(0xFFFFFFFFu, d0, o);
            d1 += __shfl_xor_sync(0xFFFFFFFFu, d1, o);
        }
        int rl = warpM * 64 + mt * 16 + (lane >> 2);
        if ((lane & 3) == 0) {
            atomicAdd(&sh_s[rl], s0);     atomicAdd(&sh_d[rl], d0);
            atomicAdd(&sh_s[rl + 8], s1); atomicAdd(&sh_d[rl + 8], d1);
        }
        int gr0 = row0 + rl;
        #pragma unroll
        for (int nt = 0; nt < 4; nt++) {
            int c = head * H1 + colb + nt * 8 + 2 * (lane & 3);
            float2 v0 = { acc[mt][nt][0], acc[mt][nt][1] };
            float2 v1 = { acc[mt][nt][2], acc[mt][nt][3] };
            *(float2*)&g_Hall[(size_t)gr0 * HCAT + c]       = v0;
            *(float2*)&g_Hall[(size_t)(gr0 + 8) * HCAT + c] = v1;
        }
    }
    __syncthreads();
    if (tid < BM) {
        g_f1s[head][row0 + tid] = sh_s[tid];
        g_f1d[head][row0 + tid] = sh_d[tid];
    }
}

// ---------------------------------------------------------------------------
// Layer-1 attention + aggregate (float4, neighbor-parallel) + relu, FUSED with
// layer-2 input GEMM (h2 = h1 @ W2) and f2s/f2d. One block per node.
// ---------------------------------------------------------------------------
__global__ __launch_bounds__(256) void attn1_fused(const float* __restrict__ W2,
                                                   const float* __restrict__ a2s,
                                                   const float* __restrict__ a2d) {
    const int n = blockIdx.x;
    __shared__ int    s_nbr[MAXDEG];
    __shared__ float  s_w[2][MAXDEG];
    __shared__ float  s_red[2][2];
    __shared__ float4 s_acc[3][64];
    __shared__ float  s_h1[HCAT];
    __shared__ float  s_p[16][17];
    const int tid = threadIdx.x;
    const int deg = g_deg[n];

    if (tid < deg) s_nbr[tid] = g_nbr[(size_t)n * MAXDEG + tid];
    __syncthreads();
    if (tid < deg) {
        int m = s_nbr[tid];
        #pragma unroll
        for (int k = 0; k < 2; k++) {
            float e = g_f1s[k][n] + g_f1d[k][m];
            s_w[k][tid] = (e > 0.0f) ? e : LALPHA * e;
        }
    }
    __syncthreads();
    {
        int w = tid >> 5, lane = tid & 31;
        if (w < 2) {
            float mx = -1e30f;
            for (int i = lane; i < deg; i += 32) mx = fmaxf(mx, s_w[w][i]);
            #pragma unroll
            for (int o = 16; o; o >>= 1) mx = fmaxf(mx, __shfl_xor_sync(0xFFFFFFFFu, mx, o));
            float sm = 0.0f;
            for (int i = lane; i < deg; i += 32) sm += __expf(s_w[w][i] - mx);
            #pragma unroll
            for (int o = 16; o; o >>= 1) sm += __shfl_xor_sync(0xFFFFFFFFu, sm, o);
            if (lane == 0) { s_red[w][0] = mx; s_red[w][1] = sm; }
        }
    }
    __syncthreads();
    if (tid < deg) {
        #pragma unroll
        for (int k = 0; k < 2; k++)
            s_w[k][tid] = __expf(s_w[k][tid] - s_red[k][0]) / s_red[k][1];
    }
    __syncthreads();

    // ---- aggregation: 4 neighbor groups x 64 col-threads (float4) ----
    const int g  = tid >> 6;     // 0..3
    const int c4 = tid & 63;     // float4 column
    const int k  = c4 >> 5;      // head
    float4 acc = make_float4(0.f, 0.f, 0.f, 0.f);
    for (int i = g; i < deg; i += 4) {
        float w = s_w[k][i];
        const float4 hv = *(const float4*)&g_Hall[(size_t)s_nbr[i] * HCAT + 4 * c4];
        acc.x = fmaf(w, hv.x, acc.x);
        acc.y = fmaf(w, hv.y, acc.y);
        acc.z = fmaf(w, hv.z, acc.z);
        acc.w = fmaf(w, hv.w, acc.w);
    }
    if (g) s_acc[g - 1][c4] = acc;
    __syncthreads();
    if (g == 0) {
        #pragma unroll
        for (int j = 0; j < 3; j++) {
            float4 v = s_acc[j][c4];
            acc.x += v.x; acc.y += v.y; acc.z += v.z; acc.w += v.w;
        }
        acc.x = fmaxf(acc.x, 0.f); acc.y = fmaxf(acc.y, 0.f);
        acc.z = fmaxf(acc.z, 0.f); acc.w = fmaxf(acc.w, 0.f);
        *(float4*)&s_h1[4 * c4] = acc;          // relu(elu(z)) == relu(z)
    }
    __syncthreads();

    // ---- fused layer-2 GEMM: h2[c] = sum_f s_h1[f] * W2[f][c] ----
    const int fg = tid >> 4;     // 0..15
    const int c  = tid & 15;
    float pa = 0.0f;
    #pragma unroll
    for (int j = 0; j < 16; j++) {
        int f = fg * 16 + j;
        pa = fmaf(s_h1[f], W2[f * C_OUT + c], pa);
    }
    s_p[fg][c] = pa;
    __syncthreads();
    if (tid < 16) {
        float h2c = 0.0f;
        #pragma unroll
        for (int j = 0; j < 16; j++) h2c += s_p[j][tid];
        g_h2[n * C_OUT + tid] = h2c;
        float vs = h2c * a2s[tid];
        float vd = h2c * a2d[tid];
        #pragma unroll
        for (int o = 8; o; o >>= 1) {
            vs += __shfl_xor_sync(0x0000FFFFu, vs, o, 16);
            vd += __shfl_xor_sync(0x0000FFFFu, vd, o, 16);
        }
        if (tid == 0) { g_f2s[n] = vs; g_f2d[n] = vd; }
    }
}

// ---------------------------------------------------------------------------
// Layer-2 attention: one warp per node, neighbor-per-lane, register softmax,
// 16-float butterfly reduce. Mean over 1 head == identity.
// ---------------------------------------------------------------------------
__global__ __launch_bounds__(256) void attn2(float* __restrict__ out) {
    int wIn = threadIdx.x >> 5, lane = threadIdx.x & 31;
    int n = blockIdx.x * 8 + wIn;
    if (n >= N_NODES) return;
    int deg = g_deg[n];
    const int* nbr = g_nbr + (size_t)n * MAXDEG;
    float fsn = g_f2s[n];

    int   myn[4];
    float ev[4];
    int cnt = 0;
    float mx = -1e30f;
    for (int i = lane; i < deg; i += 32) {
        int m = nbr[i];
        float e = fsn + g_f2d[m];
        e = (e > 0.0f) ? e : LALPHA * e;
        if (cnt < 4) { myn[cnt] = m; ev[cnt] = e; cnt++; }
        mx = fmaxf(mx, e);
    }
    #pragma unroll
    for (int o = 16; o; o >>= 1) mx = fmaxf(mx, __shfl_xor_sync(0xFFFFFFFFu, mx, o));
    float sm = 0.0f;
    #pragma unroll
    for (int j = 0; j < 4; j++)
        if (j < cnt) { ev[j] = __expf(ev[j] - mx); sm += ev[j]; }
    #pragma unroll
    for (int o = 16; o; o >>= 1) sm += __shfl_xor_sync(0xFFFFFFFFu, sm, o);
    float inv = 1.0f / sm;

    float4 a0 = make_float4(0,0,0,0), a1 = make_float4(0,0,0,0);
    float4 a2 = make_float4(0,0,0,0), a3 = make_float4(0,0,0,0);
    #pragma unroll
    for (int j = 0; j < 4; j++) {
        if (j < cnt) {
            float w = ev[j];
            const float4* hp = (const float4*)&g_h2[(size_t)myn[j] * C_OUT];
            float4 v0 = hp[0], v1 = hp[1], v2 = hp[2], v3 = hp[3];
            a0.x = fmaf(w, v0.x, a0.x); a0.y = fmaf(w, v0.y, a0.y);
            a0.z = fmaf(w, v0.z, a0.z); a0.w = fmaf(w, v0.w, a0.w);
            a1.x = fmaf(w, v1.x, a1.x); a1.y = fmaf(w, v1.y, a1.y);
            a1.z = fmaf(w, v1.z, a1.z); a1.w = fmaf(w, v1.w, a1.w);
            a2.x = fmaf(w, v2.x, a2.x); a2.y = fmaf(w, v2.y, a2.y);
            a2.z = fmaf(w, v2.z, a2.z); a2.w = fmaf(w, v2.w, a2.w);
            a3.x = fmaf(w, v3.x, a3.x); a3.y = fmaf(w, v3.y, a3.y);
            a3.z = fmaf(w, v3.z, a3.z); a3.w = fmaf(w, v3.w, a3.w);
        }
    }
    #pragma unroll
    for (int o = 16; o; o >>= 1) {
        a0.x += __shfl_xor_sync(0xFFFFFFFFu, a0.x, o);
        a0.y += __shfl_xor_sync(0xFFFFFFFFu, a0.y, o);
        a0.z += __shfl_xor_sync(0xFFFFFFFFu, a0.z, o);
        a0.w += __shfl_xor_sync(0xFFFFFFFFu, a0.w, o);
        a1.x += __shfl_xor_sync(0xFFFFFFFFu, a1.x, o);
        a1.y += __shfl_xor_sync(0xFFFFFFFFu, a1.y, o);
        a1.z += __shfl_xor_sync(0xFFFFFFFFu, a1.z, o);
        a1.w += __shfl_xor_sync(0xFFFFFFFFu, a1.w, o);
        a2.x += __shfl_xor_sync(0xFFFFFFFFu, a2.x, o);
        a2.y += __shfl_xor_sync(0xFFFFFFFFu, a2.y, o);
        a2.z += __shfl_xor_sync(0xFFFFFFFFu, a2.z, o);
        a2.w += __shfl_xor_sync(0xFFFFFFFFu, a2.w, o);
        a3.x += __shfl_xor_sync(0xFFFFFFFFu, a3.x, o);
        a3.y += __shfl_xor_sync(0xFFFFFFFFu, a3.y, o);
        a3.z += __shfl_xor_sync(0xFFFFFFFFu, a3.z, o);
        a3.w += __shfl_xor_sync(0xFFFFFFFFu, a3.w, o);
    }
    if (lane == 0) {
        float4* op = (float4*)&out[(size_t)n * C_OUT];
        a0.x *= inv; a0.y *= inv; a0.z *= inv; a0.w *= inv;
        a1.x *= inv; a1.y *= inv; a1.z *= inv; a1.w *= inv;
        a2.x *= inv; a2.y *= inv; a2.z *= inv; a2.w *= inv;
        a3.x *= inv; a3.y *= inv; a3.z *= inv; a3.w *= inv;
        op[0] = a0; op[1] = a1; op[2] = a2; op[3] = a3;
    }
}

// ---------------------------------------------------------------------------
extern "C" void kernel_launch(void* const* d_in, const int* in_sizes, int n_in,
                              void* d_out, int out_size) {
    const float* x   = (const float*)d_in[0];
    const void*  adj = d_in[1];
    const float* W1  = (const float*)d_in[2];
    const float* a1s = (const float*)d_in[3];
    const float* a1d = (const float*)d_in[4];
    const float* W2  = (const float*)d_in[5];
    const float* a2s = (const float*)d_in[6];
    const float* a2d = (const float*)d_in[7];
    float* out = (float*)d_out;

    build_csr<<<N_NODES / 8, 256>>>(adj);

    dim3 g1(KHEADS, N_NODES / BM);             // (2, 64)
    gemm1_tc<<<g1, 256>>>(x, W1, a1s, a1d);

    attn1_fused<<<N_NODES, 256>>>(W2, a2s, a2d);
    attn2<<<N_NODES / 8, 256>>>(out);
}

// round 4
// speedup vs baseline: 1.3827x; 1.0090x over previous
#include <cuda_runtime.h>

// ---------------------------------------------------------------------------
// GAT 2-layer forward, sparse-aware.
// Round 4: gemm1_tc BM=64 (256 CTAs, occ 2/SM), build_csr via warp scan.
// ---------------------------------------------------------------------------

#define N_NODES 8192
#define F_IN    512
#define H1      128
#define KHEADS  2
#define HCAT    256
#define C_OUT   16
#define MAXDEG  256
#define LALPHA  0.2f

// ---- scratch (device globals; no allocation allowed) ----
__device__ int   g_deg[N_NODES];
__device__ int   g_nbr[N_NODES * MAXDEG];
__device__ float g_Hall[N_NODES * HCAT];
__device__ float g_f1s[KHEADS][N_NODES];
__device__ float g_f1d[KHEADS][N_NODES];
__device__ float g_h2[N_NODES * C_OUT];
__device__ float g_f2s[N_NODES];
__device__ float g_f2d[N_NODES];

// ---------------------------------------------------------------------------
// CSR build, one warp per row. Per-lane byte counts + shfl exclusive scan
// (replaces 4 ballot/popc chains per 128B chunk).
// ---------------------------------------------------------------------------
__global__ __launch_bounds__(256) void build_csr(const void* adjv) {
    int warp = (blockIdx.x * blockDim.x + threadIdx.x) >> 5;
    int lane = threadIdx.x & 31;
    if (warp >= N_NODES) return;
    int row = warp;

    const unsigned char* a8 = (const unsigned char*)adjv;
    int mode;
    if ((a8[8193] | a8[3 * 8193] | a8[5 * 8193]) != 0) mode = 0;
    else mode = (((const int*)adjv)[8193] == 1) ? 1 : 2;

    int cnt = 0;
    int* nbr = g_nbr + (size_t)row * MAXDEG;

    if (mode == 0) {
        const uchar4* p = (const uchar4*)(a8 + (size_t)row * N_NODES);
        for (int base = 0; base < N_NODES / 4; base += 32) {
            uchar4 v = p[base + lane];
            int c0 = (v.x != 0), c1 = (v.y != 0), c2 = (v.z != 0), c3 = (v.w != 0);
            int myc = c0 + c1 + c2 + c3;
            int scan = myc;
            #pragma unroll
            for (int o = 1; o < 32; o <<= 1) {
                int t = __shfl_up_sync(0xFFFFFFFFu, scan, o);
                if (lane >= o) scan += t;
            }
            int pos = cnt + scan - myc;
            int col = (base + lane) * 4;
            if (c0 && pos < MAXDEG) nbr[pos++] = col;
            if (c1 && pos < MAXDEG) nbr[pos++] = col + 1;
            if (c2 && pos < MAXDEG) nbr[pos++] = col + 2;
            if (c3 && pos < MAXDEG) nbr[pos++] = col + 3;
            cnt += __shfl_sync(0xFFFFFFFFu, scan, 31);
        }
    } else if (mode == 1) {
        const int* p = (const int*)adjv + (size_t)row * N_NODES;
        for (int base = 0; base < N_NODES; base += 32) {
            bool pr = (p[base + lane] != 0);
            unsigned m = __ballot_sync(0xFFFFFFFFu, pr);
            if (pr) {
                int pos = cnt + __popc(m & ((1u << lane) - 1u));
                if (pos < MAXDEG) nbr[pos] = base + lane;
            }
            cnt += __popc(m);
        }
    } else {
        const float* p = (const float*)adjv + (size_t)row * N_NODES;
        for (int base = 0; base < N_NODES; base += 32) {
            bool pr = (p[base + lane] != 0.0f);
            unsigned m = __ballot_sync(0xFFFFFFFFu, pr);
            if (pr) {
                int pos = cnt + __popc(m & ((1u << lane) - 1u));
                if (pos < MAXDEG) nbr[pos] = base + lane;
            }
            cnt += __popc(m);
        }
    }
    if (lane == 0) g_deg[row] = (cnt < MAXDEG) ? cnt : MAXDEG;
}

// ---------------------------------------------------------------------------
// GEMM1 on tensor cores (tf32 3-term split), fused f1s/f1d epilogue.
// BM=64 so grid = 256 CTAs; 2 CTAs/SM for latency hiding.
// ---------------------------------------------------------------------------
#define BM 64
#define BK 16
#define A_STRIDE 20
#define B_STRIDE 136

__device__ __forceinline__ void split_tf32(float v, unsigned& hi, unsigned& lo) {
    asm("cvt.rna.tf32.f32 %0, %1;" : "=r"(hi) : "f"(v));
    float r = v - __uint_as_float(hi);
    asm("cvt.rna.tf32.f32 %0, %1;" : "=r"(lo) : "f"(r));
}

#define MMA_TF32(c, a0, a1, a2, a3, b0, b1)                                     \
    asm volatile(                                                               \
        "mma.sync.aligned.m16n8k8.row.col.f32.tf32.tf32.f32 "                   \
        "{%0,%1,%2,%3},{%4,%5,%6,%7},{%8,%9},{%0,%1,%2,%3};"                    \
        : "+f"(c[0]), "+f"(c[1]), "+f"(c[2]), "+f"(c[3])                        \
        : "r"(a0), "r"(a1), "r"(a2), "r"(a3), "r"(b0), "r"(b1))

__global__ __launch_bounds__(256, 2) void gemm1_tc(const float* __restrict__ x,
                                                   const float* __restrict__ W1,
                                                   const float* __restrict__ a1s,
                                                   const float* __restrict__ a1d) {
    __shared__ unsigned As_hi[BM][A_STRIDE];
    __shared__ unsigned As_lo[BM][A_STRIDE];
    __shared__ unsigned Bs_hi[BK][B_STRIDE];
    __shared__ unsigned Bs_lo[BK][B_STRIDE];
    __shared__ float sh_s[BM];
    __shared__ float sh_d[BM];

    const int head = blockIdx.x;
    const int row0 = blockIdx.y * BM;
    const int tid  = threadIdx.x;
    const int warp = tid >> 5;
    const int lane = tid & 31;
    const int warpM = warp >> 2;    // 0..1 (32 rows each)
    const int warpN = warp & 3;     // 0..3 (32 cols each)
    const float* Wh = W1 + (size_t)head * F_IN * H1;

    if (tid < BM) { sh_s[tid] = 0.0f; sh_d[tid] = 0.0f; }

    float acc[2][4][4];
    #pragma unroll
    for (int mt = 0; mt < 2; mt++)
        #pragma unroll
        for (int nt = 0; nt < 4; nt++)
            #pragma unroll
            for (int r = 0; r < 4; r++) acc[mt][nt][r] = 0.0f;

    // loader maps: A = 64x16 floats = 256 float4 (1/thread); B = 512 float4 (2/thread)
    const int aM  = tid >> 2;
    const int aK4 = (tid & 3) * 4;
    const int bK[2]  = { (0 * 256 + tid) >> 5,       (1 * 256 + tid) >> 5 };
    const int bN4[2] = { ((0 * 256 + tid) & 31) * 4, ((1 * 256 + tid) & 31) * 4 };

    float4 ax, bw[2];
    ax = *(const float4*)(x + (size_t)(row0 + aM) * F_IN + aK4);
    #pragma unroll
    for (int it = 0; it < 2; it++)
        bw[it] = *(const float4*)(Wh + (size_t)bK[it] * H1 + bN4[it]);

    for (int k0 = 0; k0 < F_IN; k0 += BK) {
        {
            uint4 h, l;
            split_tf32(ax.x, h.x, l.x);
            split_tf32(ax.y, h.y, l.y);
            split_tf32(ax.z, h.z, l.z);
            split_tf32(ax.w, h.w, l.w);
            *(uint4*)&As_hi[aM][aK4] = h;
            *(uint4*)&As_lo[aM][aK4] = l;
            #pragma unroll
            for (int it = 0; it < 2; it++) {
                split_tf32(bw[it].x, h.x, l.x);
                split_tf32(bw[it].y, h.y, l.y);
                split_tf32(bw[it].z, h.z, l.z);
                split_tf32(bw[it].w, h.w, l.w);
                *(uint4*)&Bs_hi[bK[it]][bN4[it]] = h;
                *(uint4*)&Bs_lo[bK[it]][bN4[it]] = l;
            }
        }
        __syncthreads();

        if (k0 + BK < F_IN) {
            ax = *(const float4*)(x + (size_t)(row0 + aM) * F_IN + (k0 + BK) + aK4);
            #pragma unroll
            for (int it = 0; it < 2; it++)
                bw[it] = *(const float4*)(Wh + (size_t)(k0 + BK + bK[it]) * H1 + bN4[it]);
        }

        #pragma unroll
        for (int ks = 0; ks < 2; ks++) {
            const int kb = ks * 8;
            unsigned ah[2][4], al[2][4], bh[4][2], bl[4][2];
            const int ar = warpM * 32 + (lane >> 2);
            const int kc = kb + (lane & 3);
            #pragma unroll
            for (int mt = 0; mt < 2; mt++) {
                int r = ar + mt * 16;
                ah[mt][0] = As_hi[r][kc];     ah[mt][1] = As_hi[r + 8][kc];
                ah[mt][2] = As_hi[r][kc + 4]; ah[mt][3] = As_hi[r + 8][kc + 4];
                al[mt][0] = As_lo[r][kc];     al[mt][1] = As_lo[r + 8][kc];
                al[mt][2] = As_lo[r][kc + 4]; al[mt][3] = As_lo[r + 8][kc + 4];
            }
            const int bn = warpN * 32 + (lane >> 2);
            const int kr = kb + (lane & 3);
            #pragma unroll
            for (int nt = 0; nt < 4; nt++) {
                bh[nt][0] = Bs_hi[kr][bn + nt * 8];
                bh[nt][1] = Bs_hi[kr + 4][bn + nt * 8];
                bl[nt][0] = Bs_lo[kr][bn + nt * 8];
                bl[nt][1] = Bs_lo[kr + 4][bn + nt * 8];
            }
            #pragma unroll
            for (int mt = 0; mt < 2; mt++)
                #pragma unroll
                for (int nt = 0; nt < 4; nt++) {
                    MMA_TF32(acc[mt][nt], ah[mt][0], ah[mt][1], ah[mt][2], ah[mt][3],
                             bh[nt][0], bh[nt][1]);
                    MMA_TF32(acc[mt][nt], ah[mt][0], ah[mt][1], ah[mt][2], ah[mt][3],
                             bl[nt][0], bl[nt][1]);
                    MMA_TF32(acc[mt][nt], al[mt][0], al[mt][1], al[mt][2], al[mt][3],
                             bh[nt][0], bh[nt][1]);
                }
        }
        __syncthreads();
    }

    // ---- epilogue: store Hall + fused f1s/f1d ----
    float asv[4][2], adv[4][2];
    const int colb = warpN * 32;
    #pragma unroll
    for (int nt = 0; nt < 4; nt++) {
        int c = colb + nt * 8 + 2 * (lane & 3);
        asv[nt][0] = a1s[head * H1 + c];
        asv[nt][1] = a1s[head * H1 + c + 1];
        adv[nt][0] = a1d[head * H1 + c];
        adv[nt][1] = a1d[head * H1 + c + 1];
    }

    #pragma unroll
    for (int mt = 0; mt < 2; mt++) {
        float s0 = 0.f, s1 = 0.f, d0 = 0.f, d1 = 0.f;
        #pragma unroll
        for (int nt = 0; nt < 4; nt++) {
            s0 += acc[mt][nt][0] * asv[nt][0] + acc[mt][nt][1] * asv[nt][1];
            s1 += acc[mt][nt][2] * asv[nt][0] + acc[mt][nt][3] * asv[nt][1];
            d0 += acc[mt][nt][0] * adv[nt][0] + acc[mt][nt][1] * adv[nt][1];
            d1 += acc[mt][nt][2] * adv[nt][0] + acc[mt][nt][3] * adv[nt][1];
        }
        #pragma unroll
        for (int o = 1; o <= 2; o <<= 1) {
            s0 += __shfl_xor_sync(0xFFFFFFFFu, s0, o);
            s1 += __shfl_xor_sync(0xFFFFFFFFu, s1, o);
            d0 += __shfl_xor_sync(0xFFFFFFFFu, d0, o);
            d1 += __shfl_xor_sync(0xFFFFFFFFu, d1, o);
        }
        int rl = warpM * 32 + mt * 16 + (lane >> 2);
        if ((lane & 3) == 0) {
            atomicAdd(&sh_s[rl], s0);     atomicAdd(&sh_d[rl], d0);
            atomicAdd(&sh_s[rl + 8], s1); atomicAdd(&sh_d[rl + 8], d1);
        }
        int gr0 = row0 + rl;
        #pragma unroll
        for (int nt = 0; nt < 4; nt++) {
            int c = head * H1 + colb + nt * 8 + 2 * (lane & 3);
            float2 v0 = { acc[mt][nt][0], acc[mt][nt][1] };
            float2 v1 = { acc[mt][nt][2], acc[mt][nt][3] };
            *(float2*)&g_Hall[(size_t)gr0 * HCAT + c]       = v0;
            *(float2*)&g_Hall[(size_t)(gr0 + 8) * HCAT + c] = v1;
        }
    }
    __syncthreads();
    if (tid < BM) {
        g_f1s[head][row0 + tid] = sh_s[tid];
        g_f1d[head][row0 + tid] = sh_d[tid];
    }
}

// ---------------------------------------------------------------------------
// Layer-1 attention + aggregate (float4, neighbor-parallel) + relu, FUSED with
// layer-2 input GEMM (h2 = h1 @ W2) and f2s/f2d. One block per node.
// ---------------------------------------------------------------------------
__global__ __launch_bounds__(256) void attn1_fused(const float* __restrict__ W2,
                                                   const float* __restrict__ a2s,
                                                   const float* __restrict__ a2d) {
    const int n = blockIdx.x;
    __shared__ int    s_nbr[MAXDEG];
    __shared__ float  s_w[2][MAXDEG];
    __shared__ float  s_red[2][2];
    __shared__ float4 s_acc[3][64];
    __shared__ float  s_h1[HCAT];
    __shared__ float  s_p[16][17];
    const int tid = threadIdx.x;
    const int deg = g_deg[n];

    if (tid < deg) s_nbr[tid] = g_nbr[(size_t)n * MAXDEG + tid];
    __syncthreads();
    if (tid < deg) {
        int m = s_nbr[tid];
        #pragma unroll
        for (int k = 0; k < 2; k++) {
            float e = g_f1s[k][n] + g_f1d[k][m];
            s_w[k][tid] = (e > 0.0f) ? e : LALPHA * e;
        }
    }
    __syncthreads();
    {
        int w = tid >> 5, lane = tid & 31;
        if (w < 2) {
            float mx = -1e30f;
            for (int i = lane; i < deg; i += 32) mx = fmaxf(mx, s_w[w][i]);
            #pragma unroll
            for (int o = 16; o; o >>= 1) mx = fmaxf(mx, __shfl_xor_sync(0xFFFFFFFFu, mx, o));
            float sm = 0.0f;
            for (int i = lane; i < deg; i += 32) sm += __expf(s_w[w][i] - mx);
            #pragma unroll
            for (int o = 16; o; o >>= 1) sm += __shfl_xor_sync(0xFFFFFFFFu, sm, o);
            if (lane == 0) { s_red[w][0] = mx; s_red[w][1] = sm; }
        }
    }
    __syncthreads();
    if (tid < deg) {
        #pragma unroll
        for (int k = 0; k < 2; k++)
            s_w[k][tid] = __expf(s_w[k][tid] - s_red[k][0]) / s_red[k][1];
    }
    __syncthreads();

    const int g  = tid >> 6;
    const int c4 = tid & 63;
    const int k  = c4 >> 5;
    float4 acc = make_float4(0.f, 0.f, 0.f, 0.f);
    for (int i = g; i < deg; i += 4) {
        float w = s_w[k][i];
        const float4 hv = *(const float4*)&g_Hall[(size_t)s_nbr[i] * HCAT + 4 * c4];
        acc.x = fmaf(w, hv.x, acc.x);
        acc.y = fmaf(w, hv.y, acc.y);
        acc.z = fmaf(w, hv.z, acc.z);
        acc.w = fmaf(w, hv.w, acc.w);
    }
    if (g) s_acc[g - 1][c4] = acc;
    __syncthreads();
    if (g == 0) {
        #pragma unroll
        for (int j = 0; j < 3; j++) {
            float4 v = s_acc[j][c4];
            acc.x += v.x; acc.y += v.y; acc.z += v.z; acc.w += v.w;
        }
        acc.x = fmaxf(acc.x, 0.f); acc.y = fmaxf(acc.y, 0.f);
        acc.z = fmaxf(acc.z, 0.f); acc.w = fmaxf(acc.w, 0.f);
        *(float4*)&s_h1[4 * c4] = acc;
    }
    __syncthreads();

    const int fg = tid >> 4;
    const int c  = tid & 15;
    float pa = 0.0f;
    #pragma unroll
    for (int j = 0; j < 16; j++) {
        int f = fg * 16 + j;
        pa = fmaf(s_h1[f], W2[f * C_OUT + c], pa);
    }
    s_p[fg][c] = pa;
    __syncthreads();
    if (tid < 16) {
        float h2c = 0.0f;
        #pragma unroll
        for (int j = 0; j < 16; j++) h2c += s_p[j][tid];
        g_h2[n * C_OUT + tid] = h2c;
        float vs = h2c * a2s[tid];
        float vd = h2c * a2d[tid];
        #pragma unroll
        for (int o = 8; o; o >>= 1) {
            vs += __shfl_xor_sync(0x0000FFFFu, vs, o, 16);
            vd += __shfl_xor_sync(0x0000FFFFu, vd, o, 16);
        }
        if (tid == 0) { g_f2s[n] = vs; g_f2d[n] = vd; }
    }
}

// ---------------------------------------------------------------------------
// Layer-2 attention: one warp per node, neighbor-per-lane.
// ---------------------------------------------------------------------------
__global__ __launch_bounds__(256) void attn2(float* __restrict__ out) {
    int wIn = threadIdx.x >> 5, lane = threadIdx.x & 31;
    int n = blockIdx.x * 8 + wIn;
    if (n >= N_NODES) return;
    int deg = g_deg[n];
    const int* nbr = g_nbr + (size_t)n * MAXDEG;
    float fsn = g_f2s[n];

    int   myn[4];
    float ev[4];
    int cnt = 0;
    float mx = -1e30f;
    for (int i = lane; i < deg; i += 32) {
        int m = nbr[i];
        float e = fsn + g_f2d[m];
        e = (e > 0.0f) ? e : LALPHA * e;
        if (cnt < 4) { myn[cnt] = m; ev[cnt] = e; cnt++; }
        mx = fmaxf(mx, e);
    }
    #pragma unroll
    for (int o = 16; o; o >>= 1) mx = fmaxf(mx, __shfl_xor_sync(0xFFFFFFFFu, mx, o));
    float sm = 0.0f;
    #pragma unroll
    for (int j = 0; j < 4; j++)
        if (j < cnt) { ev[j] = __expf(ev[j] - mx); sm += ev[j]; }
    #pragma unroll
    for (int o = 16; o; o >>= 1) sm += __shfl_xor_sync(0xFFFFFFFFu, sm, o);
    float inv = 1.0f / sm;

    float4 a0 = make_float4(0,0,0,0), a1 = make_float4(0,0,0,0);
    float4 a2 = make_float4(0,0,0,0), a3 = make_float4(0,0,0,0);
    #pragma unroll
    for (int j = 0; j < 4; j++) {
        if (j < cnt) {
            float w = ev[j];
            const float4* hp = (const float4*)&g_h2[(size_t)myn[j] * C_OUT];
            float4 v0 = hp[0], v1 = hp[1], v2 = hp[2], v3 = hp[3];
            a0.x = fmaf(w, v0.x, a0.x); a0.y = fmaf(w, v0.y, a0.y);
            a0.z = fmaf(w, v0.z, a0.z); a0.w = fmaf(w, v0.w, a0.w);
            a1.x = fmaf(w, v1.x, a1.x); a1.y = fmaf(w, v1.y, a1.y);
            a1.z = fmaf(w, v1.z, a1.z); a1.w = fmaf(w, v1.w, a1.w);
            a2.x = fmaf(w, v2.x, a2.x); a2.y = fmaf(w, v2.y, a2.y);
            a2.z = fmaf(w, v2.z, a2.z); a2.w = fmaf(w, v2.w, a2.w);
            a3.x = fmaf(w, v3.x, a3.x); a3.y = fmaf(w, v3.y, a3.y);
            a3.z = fmaf(w, v3.z, a3.z); a3.w = fmaf(w, v3.w, a3.w);
        }
    }
    #pragma unroll
    for (int o = 16; o; o >>= 1) {
        a0.x += __shfl_xor_sync(0xFFFFFFFFu, a0.x, o);
        a0.y += __shfl_xor_sync(0xFFFFFFFFu, a0.y, o);
        a0.z += __shfl_xor_sync(0xFFFFFFFFu, a0.z, o);
        a0.w += __shfl_xor_sync(0xFFFFFFFFu, a0.w, o);
        a1.x += __shfl_xor_sync(0xFFFFFFFFu, a1.x, o);
        a1.y += __shfl_xor_sync(0xFFFFFFFFu, a1.y, o);
        a1.z += __shfl_xor_sync(0xFFFFFFFFu, a1.z, o);
        a1.w += __shfl_xor_sync(0xFFFFFFFFu, a1.w, o);
        a2.x += __shfl_xor_sync(0xFFFFFFFFu, a2.x, o);
        a2.y += __shfl_xor_sync(0xFFFFFFFFu, a2.y, o);
        a2.z += __shfl_xor_sync(0xFFFFFFFFu, a2.z, o);
        a2.w += __shfl_xor_sync(0xFFFFFFFFu, a2.w, o);
        a3.x += __shfl_xor_sync(0xFFFFFFFFu, a3.x, o);
        a3.y += __shfl_xor_sync(0xFFFFFFFFu, a3.y, o);
        a3.z += __shfl_xor_sync(0xFFFFFFFFu, a3.z, o);
        a3.w += __shfl_xor_sync(0xFFFFFFFFu, a3.w, o);
    }
    if (lane == 0) {
        float4* op = (float4*)&out[(size_t)n * C_OUT];
        a0.x *= inv; a0.y *= inv; a0.z *= inv; a0.w *= inv;
        a1.x *= inv; a1.y *= inv; a1.z *= inv; a1.w *= inv;
        a2.x *= inv; a2.y *= inv; a2.z *= inv; a2.w *= inv;
        a3.x *= inv; a3.y *= inv; a3.z *= inv; a3.w *= inv;
        op[0] = a0; op[1] = a1; op[2] = a2; op[3] = a3;
    }
}

// ---------------------------------------------------------------------------
extern "C" void kernel_launch(void* const* d_in, const int* in_sizes, int n_in,
                              void* d_out, int out_size) {
    const float* x   = (const float*)d_in[0];
    const void*  adj = d_in[1];
    const float* W1  = (const float*)d_in[2];
    const float* a1s = (const float*)d_in[3];
    const float* a1d = (const float*)d_in[4];
    const float* W2  = (const float*)d_in[5];
    const float* a2s = (const float*)d_in[6];
    const float* a2d = (const float*)d_in[7];
    float* out = (float*)d_out;

    build_csr<<<N_NODES / 8, 256>>>(adj);

    dim3 g1(KHEADS, N_NODES / BM);             // (2, 128) = 256 CTAs
    gemm1_tc<<<g1, 256>>>(x, W1, a1s, a1d);

    attn1_fused<<<N_NODES, 256>>>(W2, a2s, a2d);
    attn2<<<N_NODES / 8, 256>>>(out);
}